// round 4
// baseline (speedup 1.0000x reference)
#include <cuda_runtime.h>

#define D 128
#define C 32
#define LSEQ 4096
#define BH 32
#define NCHUNK 128              // chunks per (b,h)
#define NC_TOTAL 4096           // total chunks
#define ASTR 33                 // 32x32 matrix row stride (pad 1)
#define RSTR 132                // 32x128 chunk row stride (pad 4, keeps 16B align)
#define VSLICE 32               // dv slice width per scan CTA
#define NSPLIT 4                // dv splits

// Scratch (allocation-free rule: __device__ globals)
__device__ float g_qn[BH * LSEQ * D];
__device__ float g_kn[BH * LSEQ * D];
__device__ float g_w [BH * LSEQ * D];
__device__ float g_u [BH * LSEQ * D];
__device__ float g_attn[NC_TOTAL * C * C];

// ---------------------------------------------------------------------------
// Kernel A: per-chunk preprocessing.
// One CTA (256 thr) per chunk: l2norm q/k, v*beta, k_beta,
// T = -(kb @ kn^T) strict-lower, forward substitution -> inv,
// u = inv@v, w = inv@kb, attn = (qn@kn^T) masked (incl diag).
// ---------------------------------------------------------------------------
__global__ void __launch_bounds__(256, 2) prep_kernel(
    const float* __restrict__ q, const float* __restrict__ k,
    const float* __restrict__ v, const float* __restrict__ beta)
{
    extern __shared__ float s[];
    float* sqn = s;                       // 32 x RSTR
    float* skn = sqn + C * RSTR;          // 32 x RSTR
    float* skb = skn + C * RSTR;          // 32 x RSTR
    float* sv  = skb + C * RSTR;          // 32 x RSTR
    float* sA  = sv  + C * RSTR;          // 32 x ASTR

    const int nc  = blockIdx.x;
    const int t   = threadIdx.x;
    const int w   = t >> 5;
    const int lid = t & 31;
    const size_t base = (size_t)nc * (C * D);

    // ---- Phase 1: normalize + scale (warp w handles rows 4w..4w+3) ----
    #pragma unroll
    for (int rr = 0; rr < 4; rr++) {
        const int r = w * 4 + rr;
        const float bet = __ldg(beta + (size_t)nc * C + r);
        float4 q4 = *(const float4*)(q + base + r * D + lid * 4);
        float4 k4 = *(const float4*)(k + base + r * D + lid * 4);
        float4 v4 = *(const float4*)(v + base + r * D + lid * 4);
        float qs = q4.x*q4.x + q4.y*q4.y + q4.z*q4.z + q4.w*q4.w;
        float ks = k4.x*k4.x + k4.y*k4.y + k4.z*k4.z + k4.w*k4.w;
        #pragma unroll
        for (int o = 16; o > 0; o >>= 1) {
            qs += __shfl_xor_sync(0xffffffffu, qs, o);
            ks += __shfl_xor_sync(0xffffffffu, ks, o);
        }
        const float qr = rsqrtf(qs + 1e-6f);
        const float kr = rsqrtf(ks + 1e-6f);
        float4 qn = make_float4(q4.x*qr, q4.y*qr, q4.z*qr, q4.w*qr);
        float4 kn = make_float4(k4.x*kr, k4.y*kr, k4.z*kr, k4.w*kr);
        float4 kb = make_float4(kn.x*bet, kn.y*bet, kn.z*bet, kn.w*bet);
        float4 vb = make_float4(v4.x*bet, v4.y*bet, v4.z*bet, v4.w*bet);
        *(float4*)(sqn + r * RSTR + lid * 4) = qn;
        *(float4*)(skn + r * RSTR + lid * 4) = kn;
        *(float4*)(skb + r * RSTR + lid * 4) = kb;
        *(float4*)(sv  + r * RSTR + lid * 4) = vb;
        *(float4*)(g_qn + base + r * D + lid * 4) = qn;
        *(float4*)(g_kn + base + r * D + lid * 4) = kn;
    }
    __syncthreads();

    // ---- Phase 2: A (strict-lower, negated) and attn (lower incl diag) ----
    // warp w computes rows i0..i0+3, lane = column j. skn read is
    // conflict-free (stride 132 -> bank (4j+d)%32 distinct over lanes).
    {
        const int j  = lid;
        const int i0 = w * 4;
        float accA0=0.f, accA1=0.f, accA2=0.f, accA3=0.f;
        float accT0=0.f, accT1=0.f, accT2=0.f, accT3=0.f;
        #pragma unroll 4
        for (int d = 0; d < D; d++) {
            const float kj = skn[j * RSTR + d];
            accA0 += skb[(i0+0)*RSTR + d] * kj;
            accA1 += skb[(i0+1)*RSTR + d] * kj;
            accA2 += skb[(i0+2)*RSTR + d] * kj;
            accA3 += skb[(i0+3)*RSTR + d] * kj;
            accT0 += sqn[(i0+0)*RSTR + d] * kj;
            accT1 += sqn[(i0+1)*RSTR + d] * kj;
            accT2 += sqn[(i0+2)*RSTR + d] * kj;
            accT3 += sqn[(i0+3)*RSTR + d] * kj;
        }
        float* ga = g_attn + (size_t)nc * (C * C);
        sA[(i0+0)*ASTR + j] = (j < i0+0) ? -accA0 : 0.f;
        sA[(i0+1)*ASTR + j] = (j < i0+1) ? -accA1 : 0.f;
        sA[(i0+2)*ASTR + j] = (j < i0+2) ? -accA2 : 0.f;
        sA[(i0+3)*ASTR + j] = (j < i0+3) ? -accA3 : 0.f;
        ga[(i0+0)*C + j] = (j <= i0+0) ? accT0 : 0.f;
        ga[(i0+1)*C + j] = (j <= i0+1) ? accT1 : 0.f;
        ga[(i0+2)*C + j] = (j <= i0+2) ? accT2 : 0.f;
        ga[(i0+3)*C + j] = (j <= i0+3) ? accT3 : 0.f;
    }
    __syncthreads();

    // ---- Phase 3: forward substitution (warp 0; lane j owns column j) ----
    // row i update: A[i][j] += sum_{k in (j,i)} A[i][k] (orig) * A[k][j] (final)
    if (w == 0) {
        const int j = lid;
        for (int i = 1; i < C; i++) {
            float acc = 0.f;
            for (int kk = j + 1; kk < i; kk++)
                acc += sA[i*ASTR + kk] * sA[kk*ASTR + j];
            __syncwarp();
            if (j < i) sA[i*ASTR + j] += acc;
            __syncwarp();
        }
        sA[j*ASTR + j] = 1.0f;   // inv = strict-lower part + I
    }
    __syncthreads();

    // ---- Phase 4: u = inv@v , w = inv@kb ----
    {
        const int i  = t >> 3;
        const int dl = (t & 7) * 4;
        #pragma unroll
        for (int db = 0; db < 4; db++) {
            const int d = db * 32 + dl;
            float4 au = make_float4(0.f,0.f,0.f,0.f);
            float4 aw = make_float4(0.f,0.f,0.f,0.f);
            #pragma unroll 8
            for (int j = 0; j < C; j++) {
                const float a = sA[i*ASTR + j];
                float4 v4 = *(float4*)(sv  + j*RSTR + d);
                float4 b4 = *(float4*)(skb + j*RSTR + d);
                au.x += a*v4.x; au.y += a*v4.y; au.z += a*v4.z; au.w += a*v4.w;
                aw.x += a*b4.x; aw.y += a*b4.y; aw.z += a*b4.z; aw.w += a*b4.w;
            }
            *(float4*)(g_u + base + i*D + d) = au;
            *(float4*)(g_w + base + i*D + d) = aw;
        }
    }
}

// ---------------------------------------------------------------------------
// Kernel B: sequential scan over chunks, parallel over (b,h) x dv-slices.
// Grid (NSPLIT, BH). Each CTA (256 thr) carries S[128, 32] in shared.
// Per chunk:  u_i = u0 - w@S ; out = q@S + attn@u_i ; S += k^T @ u_i
// ---------------------------------------------------------------------------
__global__ void __launch_bounds__(256, 2) scan_kernel(float* __restrict__ out)
{
    extern __shared__ float s[];
    float* sS  = s;                      // 128 x VSLICE (stride 32)
    float* sq  = sS  + D * VSLICE;       // 32 x RSTR
    float* sk  = sq  + C * RSTR;         // 32 x RSTR
    float* sw  = sk  + C * RSTR;         // 32 x RSTR
    float* su0 = sw  + C * RSTR;         // 32 x 32
    float* sat = su0 + C * C;            // 32 x ASTR
    float* sui = sat + C * ASTR;         // 32 x 32

    const int bh  = blockIdx.y;
    const int v0  = blockIdx.x * VSLICE;
    const int t   = threadIdx.x;
    const int c   = t >> 3;              // row 0..31
    const int v4  = (t & 7) * 4;         // slice-local col group
    const int w   = t >> 5;
    const int lid = t & 31;

    #pragma unroll
    for (int r = 0; r < 4; r++)
        *(float4*)(sS + (r * 256 + t) * 4) = make_float4(0.f,0.f,0.f,0.f);

    const size_t bhb = (size_t)bh * LSEQ * D;
    const float* gq = g_qn + bhb;
    const float* gk = g_kn + bhb;
    const float* gw = g_w  + bhb;
    const float* gu = g_u  + bhb;
    const float* ga = g_attn + (size_t)bh * NCHUNK * (C * C);

    for (int ci = 0; ci < NCHUNK; ci++) {
        __syncthreads();                 // prev chunk fully consumed
        const size_t cb = (size_t)ci * (C * D);

        // ---- load chunk data (coalesced; conflict-free row-contig stores) --
        #pragma unroll
        for (int rr = 0; rr < 4; rr++) {
            const int r = w * 4 + rr;
            float4 a  = *(const float4*)(gq + cb + r*D + lid*4);
            float4 b  = *(const float4*)(gk + cb + r*D + lid*4);
            float4 cc = *(const float4*)(gw + cb + r*D + lid*4);
            *(float4*)(sq + r*RSTR + lid*4) = a;
            *(float4*)(sk + r*RSTR + lid*4) = b;
            *(float4*)(sw + r*RSTR + lid*4) = cc;
        }
        *(float4*)(su0 + c*C + v4) = *(const float4*)(gu + cb + c*D + v0 + v4);
        {
            float4 a4 = *(const float4*)(ga + (size_t)ci * (C*C) + t*4);
            const int ai = t >> 3, aj = (t & 7) * 4;
            sat[ai*ASTR + aj+0] = a4.x;
            sat[ai*ASTR + aj+1] = a4.y;
            sat[ai*ASTR + aj+2] = a4.z;
            sat[ai*ASTR + aj+3] = a4.w;
        }
        __syncthreads();

        // ---- phase 2: aU = w@S , aQ = q@S  (32x32 over d=128) ----
        float4 aU = make_float4(0.f,0.f,0.f,0.f);
        float4 aQ = make_float4(0.f,0.f,0.f,0.f);
        #pragma unroll 4
        for (int d = 0; d < D; d++) {
            const float wv = sw[c*RSTR + d];
            const float qv = sq[c*RSTR + d];
            float4 S4 = *(float4*)(sS + d*VSLICE + v4);
            aU.x += wv*S4.x; aU.y += wv*S4.y; aU.z += wv*S4.z; aU.w += wv*S4.w;
            aQ.x += qv*S4.x; aQ.y += qv*S4.y; aQ.z += qv*S4.z; aQ.w += qv*S4.w;
        }
        float4 u0 = *(float4*)(su0 + c*C + v4);
        float4 ui = make_float4(u0.x - aU.x, u0.y - aU.y, u0.z - aU.z, u0.w - aU.w);
        *(float4*)(sui + c*C + v4) = ui;
        __syncthreads();

        // ---- phase 3: out = aQ + attn @ u_i ----
        float4 aO = aQ;
        #pragma unroll 8
        for (int e = 0; e < C; e++) {
            const float a = sat[c*ASTR + e];
            float4 u4 = *(float4*)(sui + e*C + v4);
            aO.x += a*u4.x; aO.y += a*u4.y; aO.z += a*u4.z; aO.w += a*u4.w;
        }
        *(float4*)(out + bhb + cb + c*D + v0 + v4) = aO;

        // ---- phase 4: S[d, v] += sum_c k[c,d] * u_i[c,v] ----
        // thread owns rows {c, c+32, c+64, c+96} x cols v4..v4+3
        float4 a0 = make_float4(0.f,0.f,0.f,0.f);
        float4 a1 = make_float4(0.f,0.f,0.f,0.f);
        float4 a2 = make_float4(0.f,0.f,0.f,0.f);
        float4 a3 = make_float4(0.f,0.f,0.f,0.f);
        #pragma unroll 4
        for (int e = 0; e < C; e++) {
            float4 u4 = *(float4*)(sui + e*C + v4);
            const float k0 = sk[e*RSTR + c];
            const float k1 = sk[e*RSTR + c + 32];
            const float k2 = sk[e*RSTR + c + 64];
            const float k3 = sk[e*RSTR + c + 96];
            a0.x += k0*u4.x; a0.y += k0*u4.y; a0.z += k0*u4.z; a0.w += k0*u4.w;
            a1.x += k1*u4.x; a1.y += k1*u4.y; a1.z += k1*u4.z; a1.w += k1*u4.w;
            a2.x += k2*u4.x; a2.y += k2*u4.y; a2.z += k2*u4.z; a2.w += k2*u4.w;
            a3.x += k3*u4.x; a3.y += k3*u4.y; a3.z += k3*u4.z; a3.w += k3*u4.w;
        }
        {
            float4* p0 = (float4*)(sS + (c     )*VSLICE + v4);
            float4* p1 = (float4*)(sS + (c + 32)*VSLICE + v4);
            float4* p2 = (float4*)(sS + (c + 64)*VSLICE + v4);
            float4* p3 = (float4*)(sS + (c + 96)*VSLICE + v4);
            float4 t0 = *p0, t1 = *p1, t2 = *p2, t3 = *p3;
            t0.x += a0.x; t0.y += a0.y; t0.z += a0.z; t0.w += a0.w;
            t1.x += a1.x; t1.y += a1.y; t1.z += a1.z; t1.w += a1.w;
            t2.x += a2.x; t2.y += a2.y; t2.z += a2.z; t2.w += a2.w;
            t3.x += a3.x; t3.y += a3.y; t3.z += a3.z; t3.w += a3.w;
            *p0 = t0; *p1 = t1; *p2 = t2; *p3 = t3;
        }
    }
}

// ---------------------------------------------------------------------------
extern "C" void kernel_launch(void* const* d_in, const int* in_sizes, int n_in,
                              void* d_out, int out_size)
{
    const float* q    = (const float*)d_in[0];
    const float* k    = (const float*)d_in[1];
    const float* v    = (const float*)d_in[2];
    const float* beta = (const float*)d_in[3];
    float* out = (float*)d_out;

    const size_t smemA = (size_t)(4 * C * RSTR + C * ASTR) * sizeof(float);
    const size_t smemB = (size_t)(D * VSLICE + 3 * C * RSTR + C * C + C * ASTR + C * C)
                         * sizeof(float);

    cudaFuncSetAttribute(prep_kernel, cudaFuncAttributeMaxDynamicSharedMemorySize,
                         (int)smemA);
    cudaFuncSetAttribute(scan_kernel, cudaFuncAttributeMaxDynamicSharedMemorySize,
                         (int)smemB);

    prep_kernel<<<NC_TOTAL, 256, smemA>>>(q, k, v, beta);
    scan_kernel<<<dim3(NSPLIT, BH), 256, smemB>>>(out);
}

// round 5
// speedup vs baseline: 1.0023x; 1.0023x over previous
#include <cuda_runtime.h>

#define D 128
#define C 32
#define LSEQ 4096
#define BH 32
#define NCHUNK 128              // chunks per (b,h)
#define NC_TOTAL 4096           // total chunks
#define ASTR 33                 // 32x32 matrix row stride (pad 1)
#define RSTR 132                // 32x128 chunk row stride (pad 4, keeps 16B align)
#define VSLICE 32               // dv slice width per scan CTA
#define NSPLIT 4                // dv splits

// Scratch (allocation-free rule: __device__ globals)
__device__ float g_qn[BH * LSEQ * D];
__device__ float g_kn[BH * LSEQ * D];
__device__ float g_w [BH * LSEQ * D];
__device__ float g_u [BH * LSEQ * D];
__device__ float g_attn[NC_TOTAL * C * C];

// ---------------------------------------------------------------------------
// Kernel A: per-chunk preprocessing.
// One CTA (256 thr) per chunk: l2norm q/k, v*beta, k_beta,
// T = -(kb @ kn^T) strict-lower, forward substitution -> inv,
// u = inv@v, w = inv@kb, attn = (qn@kn^T) masked (incl diag).
// ---------------------------------------------------------------------------
__global__ void __launch_bounds__(256, 2) prep_kernel(
    const float* __restrict__ q, const float* __restrict__ k,
    const float* __restrict__ v, const float* __restrict__ beta)
{
    extern __shared__ float s[];
    float* sqn = s;                       // 32 x RSTR
    float* skn = sqn + C * RSTR;          // 32 x RSTR
    float* skb = skn + C * RSTR;          // 32 x RSTR
    float* sv  = skb + C * RSTR;          // 32 x RSTR
    float* sA  = sv  + C * RSTR;          // 32 x ASTR

    const int nc  = blockIdx.x;
    const int t   = threadIdx.x;
    const int w   = t >> 5;
    const int lid = t & 31;
    const size_t base = (size_t)nc * (C * D);

    // ---- Phase 1: normalize + scale (warp w handles rows 4w..4w+3) ----
    #pragma unroll
    for (int rr = 0; rr < 4; rr++) {
        const int r = w * 4 + rr;
        const float bet = __ldg(beta + (size_t)nc * C + r);
        float4 q4 = *(const float4*)(q + base + r * D + lid * 4);
        float4 k4 = *(const float4*)(k + base + r * D + lid * 4);
        float4 v4 = *(const float4*)(v + base + r * D + lid * 4);
        float qs = q4.x*q4.x + q4.y*q4.y + q4.z*q4.z + q4.w*q4.w;
        float ks = k4.x*k4.x + k4.y*k4.y + k4.z*k4.z + k4.w*k4.w;
        #pragma unroll
        for (int o = 16; o > 0; o >>= 1) {
            qs += __shfl_xor_sync(0xffffffffu, qs, o);
            ks += __shfl_xor_sync(0xffffffffu, ks, o);
        }
        const float qr = rsqrtf(qs + 1e-6f);
        const float kr = rsqrtf(ks + 1e-6f);
        float4 qn = make_float4(q4.x*qr, q4.y*qr, q4.z*qr, q4.w*qr);
        float4 kn = make_float4(k4.x*kr, k4.y*kr, k4.z*kr, k4.w*kr);
        float4 kb = make_float4(kn.x*bet, kn.y*bet, kn.z*bet, kn.w*bet);
        float4 vb = make_float4(v4.x*bet, v4.y*bet, v4.z*bet, v4.w*bet);
        *(float4*)(sqn + r * RSTR + lid * 4) = qn;
        *(float4*)(skn + r * RSTR + lid * 4) = kn;
        *(float4*)(skb + r * RSTR + lid * 4) = kb;
        *(float4*)(sv  + r * RSTR + lid * 4) = vb;
        *(float4*)(g_qn + base + r * D + lid * 4) = qn;
        *(float4*)(g_kn + base + r * D + lid * 4) = kn;
    }
    __syncthreads();

    // ---- Phase 2: A (strict-lower, negated) and attn (lower incl diag) ----
    // warp w computes rows i0..i0+3, lane = column j. skn read is
    // conflict-free (stride 132 -> bank (4j+d)%32 distinct over lanes).
    {
        const int j  = lid;
        const int i0 = w * 4;
        float accA0=0.f, accA1=0.f, accA2=0.f, accA3=0.f;
        float accT0=0.f, accT1=0.f, accT2=0.f, accT3=0.f;
        #pragma unroll 4
        for (int d = 0; d < D; d++) {
            const float kj = skn[j * RSTR + d];
            accA0 += skb[(i0+0)*RSTR + d] * kj;
            accA1 += skb[(i0+1)*RSTR + d] * kj;
            accA2 += skb[(i0+2)*RSTR + d] * kj;
            accA3 += skb[(i0+3)*RSTR + d] * kj;
            accT0 += sqn[(i0+0)*RSTR + d] * kj;
            accT1 += sqn[(i0+1)*RSTR + d] * kj;
            accT2 += sqn[(i0+2)*RSTR + d] * kj;
            accT3 += sqn[(i0+3)*RSTR + d] * kj;
        }
        float* ga = g_attn + (size_t)nc * (C * C);
        sA[(i0+0)*ASTR + j] = (j < i0+0) ? -accA0 : 0.f;
        sA[(i0+1)*ASTR + j] = (j < i0+1) ? -accA1 : 0.f;
        sA[(i0+2)*ASTR + j] = (j < i0+2) ? -accA2 : 0.f;
        sA[(i0+3)*ASTR + j] = (j < i0+3) ? -accA3 : 0.f;
        ga[(i0+0)*C + j] = (j <= i0+0) ? accT0 : 0.f;
        ga[(i0+1)*C + j] = (j <= i0+1) ? accT1 : 0.f;
        ga[(i0+2)*C + j] = (j <= i0+2) ? accT2 : 0.f;
        ga[(i0+3)*C + j] = (j <= i0+3) ? accT3 : 0.f;
    }
    __syncthreads();

    // ---- Phase 3: forward substitution (warp 0; lane j owns column j) ----
    // row i update: A[i][j] += sum_{k in (j,i)} A[i][k] (orig) * A[k][j] (final)
    if (w == 0) {
        const int j = lid;
        for (int i = 1; i < C; i++) {
            float acc = 0.f;
            for (int kk = j + 1; kk < i; kk++)
                acc += sA[i*ASTR + kk] * sA[kk*ASTR + j];
            __syncwarp();
            if (j < i) sA[i*ASTR + j] += acc;
            __syncwarp();
        }
        sA[j*ASTR + j] = 1.0f;   // inv = strict-lower part + I
    }
    __syncthreads();

    // ---- Phase 4: u = inv@v , w = inv@kb ----
    {
        const int i  = t >> 3;
        const int dl = (t & 7) * 4;
        #pragma unroll
        for (int db = 0; db < 4; db++) {
            const int d = db * 32 + dl;
            float4 au = make_float4(0.f,0.f,0.f,0.f);
            float4 aw = make_float4(0.f,0.f,0.f,0.f);
            #pragma unroll 8
            for (int j = 0; j < C; j++) {
                const float a = sA[i*ASTR + j];
                float4 v4 = *(float4*)(sv  + j*RSTR + d);
                float4 b4 = *(float4*)(skb + j*RSTR + d);
                au.x += a*v4.x; au.y += a*v4.y; au.z += a*v4.z; au.w += a*v4.w;
                aw.x += a*b4.x; aw.y += a*b4.y; aw.z += a*b4.z; aw.w += a*b4.w;
            }
            *(float4*)(g_u + base + i*D + d) = au;
            *(float4*)(g_w + base + i*D + d) = aw;
        }
    }
}

// ---------------------------------------------------------------------------
// Kernel B: sequential scan over chunks, parallel over (b,h) x dv-slices.
// Grid (NSPLIT, BH). Each CTA (256 thr) carries S[128, 32] in shared.
// Per chunk:  u_i = u0 - w@S ; out = q@S + attn@u_i ; S += k^T @ u_i
// ---------------------------------------------------------------------------
__global__ void __launch_bounds__(256, 2) scan_kernel(float* __restrict__ out)
{
    extern __shared__ float s[];
    float* sS  = s;                      // 128 x VSLICE (stride 32)
    float* sq  = sS  + D * VSLICE;       // 32 x RSTR
    float* sk  = sq  + C * RSTR;         // 32 x RSTR
    float* sw  = sk  + C * RSTR;         // 32 x RSTR
    float* su0 = sw  + C * RSTR;         // 32 x 32
    float* sat = su0 + C * C;            // 32 x ASTR
    float* sui = sat + C * ASTR;         // 32 x 32

    const int bh  = blockIdx.y;
    const int v0  = blockIdx.x * VSLICE;
    const int t   = threadIdx.x;
    const int c   = t >> 3;              // row 0..31
    const int v4  = (t & 7) * 4;         // slice-local col group
    const int w   = t >> 5;
    const int lid = t & 31;

    #pragma unroll
    for (int r = 0; r < 4; r++)
        *(float4*)(sS + (r * 256 + t) * 4) = make_float4(0.f,0.f,0.f,0.f);

    const size_t bhb = (size_t)bh * LSEQ * D;
    const float* gq = g_qn + bhb;
    const float* gk = g_kn + bhb;
    const float* gw = g_w  + bhb;
    const float* gu = g_u  + bhb;
    const float* ga = g_attn + (size_t)bh * NCHUNK * (C * C);

    for (int ci = 0; ci < NCHUNK; ci++) {
        __syncthreads();                 // prev chunk fully consumed
        const size_t cb = (size_t)ci * (C * D);

        // ---- load chunk data (coalesced; conflict-free row-contig stores) --
        #pragma unroll
        for (int rr = 0; rr < 4; rr++) {
            const int r = w * 4 + rr;
            float4 a  = *(const float4*)(gq + cb + r*D + lid*4);
            float4 b  = *(const float4*)(gk + cb + r*D + lid*4);
            float4 cc = *(const float4*)(gw + cb + r*D + lid*4);
            *(float4*)(sq + r*RSTR + lid*4) = a;
            *(float4*)(sk + r*RSTR + lid*4) = b;
            *(float4*)(sw + r*RSTR + lid*4) = cc;
        }
        *(float4*)(su0 + c*C + v4) = *(const float4*)(gu + cb + c*D + v0 + v4);
        {
            float4 a4 = *(const float4*)(ga + (size_t)ci * (C*C) + t*4);
            const int ai = t >> 3, aj = (t & 7) * 4;
            sat[ai*ASTR + aj+0] = a4.x;
            sat[ai*ASTR + aj+1] = a4.y;
            sat[ai*ASTR + aj+2] = a4.z;
            sat[ai*ASTR + aj+3] = a4.w;
        }
        __syncthreads();

        // ---- phase 2: aU = w@S , aQ = q@S  (32x32 over d=128) ----
        float4 aU = make_float4(0.f,0.f,0.f,0.f);
        float4 aQ = make_float4(0.f,0.f,0.f,0.f);
        #pragma unroll 4
        for (int d = 0; d < D; d++) {
            const float wv = sw[c*RSTR + d];
            const float qv = sq[c*RSTR + d];
            float4 S4 = *(float4*)(sS + d*VSLICE + v4);
            aU.x += wv*S4.x; aU.y += wv*S4.y; aU.z += wv*S4.z; aU.w += wv*S4.w;
            aQ.x += qv*S4.x; aQ.y += qv*S4.y; aQ.z += qv*S4.z; aQ.w += qv*S4.w;
        }
        float4 u0 = *(float4*)(su0 + c*C + v4);
        float4 ui = make_float4(u0.x - aU.x, u0.y - aU.y, u0.z - aU.z, u0.w - aU.w);
        *(float4*)(sui + c*C + v4) = ui;
        __syncthreads();

        // ---- phase 3: out = aQ + attn @ u_i ----
        float4 aO = aQ;
        #pragma unroll 8
        for (int e = 0; e < C; e++) {
            const float a = sat[c*ASTR + e];
            float4 u4 = *(float4*)(sui + e*C + v4);
            aO.x += a*u4.x; aO.y += a*u4.y; aO.z += a*u4.z; aO.w += a*u4.w;
        }
        *(float4*)(out + bhb + cb + c*D + v0 + v4) = aO;

        // ---- phase 4: S[d, v] += sum_c k[c,d] * u_i[c,v] ----
        // thread owns rows {c, c+32, c+64, c+96} x cols v4..v4+3
        float4 a0 = make_float4(0.f,0.f,0.f,0.f);
        float4 a1 = make_float4(0.f,0.f,0.f,0.f);
        float4 a2 = make_float4(0.f,0.f,0.f,0.f);
        float4 a3 = make_float4(0.f,0.f,0.f,0.f);
        #pragma unroll 4
        for (int e = 0; e < C; e++) {
            float4 u4 = *(float4*)(sui + e*C + v4);
            const float k0 = sk[e*RSTR + c];
            const float k1 = sk[e*RSTR + c + 32];
            const float k2 = sk[e*RSTR + c + 64];
            const float k3 = sk[e*RSTR + c + 96];
            a0.x += k0*u4.x; a0.y += k0*u4.y; a0.z += k0*u4.z; a0.w += k0*u4.w;
            a1.x += k1*u4.x; a1.y += k1*u4.y; a1.z += k1*u4.z; a1.w += k1*u4.w;
            a2.x += k2*u4.x; a2.y += k2*u4.y; a2.z += k2*u4.z; a2.w += k2*u4.w;
            a3.x += k3*u4.x; a3.y += k3*u4.y; a3.z += k3*u4.z; a3.w += k3*u4.w;
        }
        {
            float4* p0 = (float4*)(sS + (c     )*VSLICE + v4);
            float4* p1 = (float4*)(sS + (c + 32)*VSLICE + v4);
            float4* p2 = (float4*)(sS + (c + 64)*VSLICE + v4);
            float4* p3 = (float4*)(sS + (c + 96)*VSLICE + v4);
            float4 t0 = *p0, t1 = *p1, t2 = *p2, t3 = *p3;
            t0.x += a0.x; t0.y += a0.y; t0.z += a0.z; t0.w += a0.w;
            t1.x += a1.x; t1.y += a1.y; t1.z += a1.z; t1.w += a1.w;
            t2.x += a2.x; t2.y += a2.y; t2.z += a2.z; t2.w += a2.w;
            t3.x += a3.x; t3.y += a3.y; t3.z += a3.z; t3.w += a3.w;
            *p0 = t0; *p1 = t1; *p2 = t2; *p3 = t3;
        }
    }
}

// ---------------------------------------------------------------------------
extern "C" void kernel_launch(void* const* d_in, const int* in_sizes, int n_in,
                              void* d_out, int out_size)
{
    const float* q    = (const float*)d_in[0];
    const float* k    = (const float*)d_in[1];
    const float* v    = (const float*)d_in[2];
    const float* beta = (const float*)d_in[3];
    float* out = (float*)d_out;

    const size_t smemA = (size_t)(4 * C * RSTR + C * ASTR) * sizeof(float);
    const size_t smemB = (size_t)(D * VSLICE + 3 * C * RSTR + C * C + C * ASTR + C * C)
                         * sizeof(float);

    cudaFuncSetAttribute(prep_kernel, cudaFuncAttributeMaxDynamicSharedMemorySize,
                         (int)smemA);
    cudaFuncSetAttribute(scan_kernel, cudaFuncAttributeMaxDynamicSharedMemorySize,
                         (int)smemB);

    prep_kernel<<<NC_TOTAL, 256, smemA>>>(q, k, v, beta);
    scan_kernel<<<dim3(NSPLIT, BH), 256, smemB>>>(out);
}

// round 6
// speedup vs baseline: 1.0040x; 1.0017x over previous
#include <cuda_runtime.h>

#define D 128
#define C 32
#define LSEQ 4096
#define BH 32
#define NCHUNK 128              // chunks per (b,h)
#define NC_TOTAL 4096           // total chunks
#define ASTR 33                 // 32x32 matrix row stride (pad 1)
#define RSTR 132                // 32x128 chunk row stride (pad 4, keeps 16B align)
#define VSLICE 32               // dv slice width per scan CTA
#define NSPLIT 4                // dv splits

// Scratch (allocation-free rule: __device__ globals)
__device__ float g_qn[BH * LSEQ * D];
__device__ float g_kn[BH * LSEQ * D];
__device__ float g_w [BH * LSEQ * D];
__device__ float g_u [BH * LSEQ * D];
__device__ float g_attn[NC_TOTAL * C * C];

// ---------------------------------------------------------------------------
// Kernel A: per-chunk preprocessing.
// One CTA (256 thr) per chunk: l2norm q/k, v*beta, k_beta,
// T = -(kb @ kn^T) strict-lower, forward substitution -> inv,
// u = inv@v, w = inv@kb, attn = (qn@kn^T) masked (incl diag).
// ---------------------------------------------------------------------------
__global__ void __launch_bounds__(256, 2) prep_kernel(
    const float* __restrict__ q, const float* __restrict__ k,
    const float* __restrict__ v, const float* __restrict__ beta)
{
    extern __shared__ float s[];
    float* sqn = s;                       // 32 x RSTR
    float* skn = sqn + C * RSTR;          // 32 x RSTR
    float* skb = skn + C * RSTR;          // 32 x RSTR
    float* sv  = skb + C * RSTR;          // 32 x RSTR
    float* sA  = sv  + C * RSTR;          // 32 x ASTR

    const int nc  = blockIdx.x;
    const int t   = threadIdx.x;
    const int w   = t >> 5;
    const int lid = t & 31;
    const size_t base = (size_t)nc * (C * D);

    // ---- Phase 1: normalize + scale (warp w handles rows 4w..4w+3) ----
    #pragma unroll
    for (int rr = 0; rr < 4; rr++) {
        const int r = w * 4 + rr;
        const float bet = __ldg(beta + (size_t)nc * C + r);
        float4 q4 = *(const float4*)(q + base + r * D + lid * 4);
        float4 k4 = *(const float4*)(k + base + r * D + lid * 4);
        float4 v4 = *(const float4*)(v + base + r * D + lid * 4);
        float qs = q4.x*q4.x + q4.y*q4.y + q4.z*q4.z + q4.w*q4.w;
        float ks = k4.x*k4.x + k4.y*k4.y + k4.z*k4.z + k4.w*k4.w;
        #pragma unroll
        for (int o = 16; o > 0; o >>= 1) {
            qs += __shfl_xor_sync(0xffffffffu, qs, o);
            ks += __shfl_xor_sync(0xffffffffu, ks, o);
        }
        const float qr = rsqrtf(qs + 1e-6f);
        const float kr = rsqrtf(ks + 1e-6f);
        float4 qn = make_float4(q4.x*qr, q4.y*qr, q4.z*qr, q4.w*qr);
        float4 kn = make_float4(k4.x*kr, k4.y*kr, k4.z*kr, k4.w*kr);
        float4 kb = make_float4(kn.x*bet, kn.y*bet, kn.z*bet, kn.w*bet);
        float4 vb = make_float4(v4.x*bet, v4.y*bet, v4.z*bet, v4.w*bet);
        *(float4*)(sqn + r * RSTR + lid * 4) = qn;
        *(float4*)(skn + r * RSTR + lid * 4) = kn;
        *(float4*)(skb + r * RSTR + lid * 4) = kb;
        *(float4*)(sv  + r * RSTR + lid * 4) = vb;
        *(float4*)(g_qn + base + r * D + lid * 4) = qn;
        *(float4*)(g_kn + base + r * D + lid * 4) = kn;
    }
    __syncthreads();

    // ---- Phase 2: A (strict-lower, negated) and attn (lower incl diag) ----
    // warp w computes rows i0..i0+3, lane = column j. skn read is
    // conflict-free (stride 132 -> bank (4j+d)%32 distinct over lanes).
    {
        const int j  = lid;
        const int i0 = w * 4;
        float accA0=0.f, accA1=0.f, accA2=0.f, accA3=0.f;
        float accT0=0.f, accT1=0.f, accT2=0.f, accT3=0.f;
        #pragma unroll 4
        for (int d = 0; d < D; d++) {
            const float kj = skn[j * RSTR + d];
            accA0 += skb[(i0+0)*RSTR + d] * kj;
            accA1 += skb[(i0+1)*RSTR + d] * kj;
            accA2 += skb[(i0+2)*RSTR + d] * kj;
            accA3 += skb[(i0+3)*RSTR + d] * kj;
            accT0 += sqn[(i0+0)*RSTR + d] * kj;
            accT1 += sqn[(i0+1)*RSTR + d] * kj;
            accT2 += sqn[(i0+2)*RSTR + d] * kj;
            accT3 += sqn[(i0+3)*RSTR + d] * kj;
        }
        float* ga = g_attn + (size_t)nc * (C * C);
        sA[(i0+0)*ASTR + j] = (j < i0+0) ? -accA0 : 0.f;
        sA[(i0+1)*ASTR + j] = (j < i0+1) ? -accA1 : 0.f;
        sA[(i0+2)*ASTR + j] = (j < i0+2) ? -accA2 : 0.f;
        sA[(i0+3)*ASTR + j] = (j < i0+3) ? -accA3 : 0.f;
        ga[(i0+0)*C + j] = (j <= i0+0) ? accT0 : 0.f;
        ga[(i0+1)*C + j] = (j <= i0+1) ? accT1 : 0.f;
        ga[(i0+2)*C + j] = (j <= i0+2) ? accT2 : 0.f;
        ga[(i0+3)*C + j] = (j <= i0+3) ? accT3 : 0.f;
    }
    __syncthreads();

    // ---- Phase 3: forward substitution (warp 0; lane j owns column j) ----
    // row i update: A[i][j] += sum_{k in (j,i)} A[i][k] (orig) * A[k][j] (final)
    if (w == 0) {
        const int j = lid;
        for (int i = 1; i < C; i++) {
            float acc = 0.f;
            for (int kk = j + 1; kk < i; kk++)
                acc += sA[i*ASTR + kk] * sA[kk*ASTR + j];
            __syncwarp();
            if (j < i) sA[i*ASTR + j] += acc;
            __syncwarp();
        }
        sA[j*ASTR + j] = 1.0f;   // inv = strict-lower part + I
    }
    __syncthreads();

    // ---- Phase 4: u = inv@v , w = inv@kb ----
    {
        const int i  = t >> 3;
        const int dl = (t & 7) * 4;
        #pragma unroll
        for (int db = 0; db < 4; db++) {
            const int d = db * 32 + dl;
            float4 au = make_float4(0.f,0.f,0.f,0.f);
            float4 aw = make_float4(0.f,0.f,0.f,0.f);
            #pragma unroll 8
            for (int j = 0; j < C; j++) {
                const float a = sA[i*ASTR + j];
                float4 v4 = *(float4*)(sv  + j*RSTR + d);
                float4 b4 = *(float4*)(skb + j*RSTR + d);
                au.x += a*v4.x; au.y += a*v4.y; au.z += a*v4.z; au.w += a*v4.w;
                aw.x += a*b4.x; aw.y += a*b4.y; aw.z += a*b4.z; aw.w += a*b4.w;
            }
            *(float4*)(g_u + base + i*D + d) = au;
            *(float4*)(g_w + base + i*D + d) = aw;
        }
    }
}

// ---------------------------------------------------------------------------
// Kernel B: sequential scan over chunks, parallel over (b,h) x dv-slices.
// Grid (NSPLIT, BH). Each CTA (256 thr) carries S[128, 32] in shared.
// Per chunk:  u_i = u0 - w@S ; out = q@S + attn@u_i ; S += k^T @ u_i
// ---------------------------------------------------------------------------
__global__ void __launch_bounds__(256, 2) scan_kernel(float* __restrict__ out)
{
    extern __shared__ float s[];
    float* sS  = s;                      // 128 x VSLICE (stride 32)
    float* sq  = sS  + D * VSLICE;       // 32 x RSTR
    float* sk  = sq  + C * RSTR;         // 32 x RSTR
    float* sw  = sk  + C * RSTR;         // 32 x RSTR
    float* su0 = sw  + C * RSTR;         // 32 x 32
    float* sat = su0 + C * C;            // 32 x ASTR
    float* sui = sat + C * ASTR;         // 32 x 32

    const int bh  = blockIdx.y;
    const int v0  = blockIdx.x * VSLICE;
    const int t   = threadIdx.x;
    const int c   = t >> 3;              // row 0..31
    const int v4  = (t & 7) * 4;         // slice-local col group
    const int w   = t >> 5;
    const int lid = t & 31;

    #pragma unroll
    for (int r = 0; r < 4; r++)
        *(float4*)(sS + (r * 256 + t) * 4) = make_float4(0.f,0.f,0.f,0.f);

    const size_t bhb = (size_t)bh * LSEQ * D;
    const float* gq = g_qn + bhb;
    const float* gk = g_kn + bhb;
    const float* gw = g_w  + bhb;
    const float* gu = g_u  + bhb;
    const float* ga = g_attn + (size_t)bh * NCHUNK * (C * C);

    for (int ci = 0; ci < NCHUNK; ci++) {
        __syncthreads();                 // prev chunk fully consumed
        const size_t cb = (size_t)ci * (C * D);

        // ---- load chunk data (coalesced; conflict-free row-contig stores) --
        #pragma unroll
        for (int rr = 0; rr < 4; rr++) {
            const int r = w * 4 + rr;
            float4 a  = *(const float4*)(gq + cb + r*D + lid*4);
            float4 b  = *(const float4*)(gk + cb + r*D + lid*4);
            float4 cc = *(const float4*)(gw + cb + r*D + lid*4);
            *(float4*)(sq + r*RSTR + lid*4) = a;
            *(float4*)(sk + r*RSTR + lid*4) = b;
            *(float4*)(sw + r*RSTR + lid*4) = cc;
        }
        *(float4*)(su0 + c*C + v4) = *(const float4*)(gu + cb + c*D + v0 + v4);
        {
            float4 a4 = *(const float4*)(ga + (size_t)ci * (C*C) + t*4);
            const int ai = t >> 3, aj = (t & 7) * 4;
            sat[ai*ASTR + aj+0] = a4.x;
            sat[ai*ASTR + aj+1] = a4.y;
            sat[ai*ASTR + aj+2] = a4.z;
            sat[ai*ASTR + aj+3] = a4.w;
        }
        __syncthreads();

        // ---- phase 2: aU = w@S , aQ = q@S  (32x32 over d=128) ----
        float4 aU = make_float4(0.f,0.f,0.f,0.f);
        float4 aQ = make_float4(0.f,0.f,0.f,0.f);
        #pragma unroll 4
        for (int d = 0; d < D; d++) {
            const float wv = sw[c*RSTR + d];
            const float qv = sq[c*RSTR + d];
            float4 S4 = *(float4*)(sS + d*VSLICE + v4);
            aU.x += wv*S4.x; aU.y += wv*S4.y; aU.z += wv*S4.z; aU.w += wv*S4.w;
            aQ.x += qv*S4.x; aQ.y += qv*S4.y; aQ.z += qv*S4.z; aQ.w += qv*S4.w;
        }
        float4 u0 = *(float4*)(su0 + c*C + v4);
        float4 ui = make_float4(u0.x - aU.x, u0.y - aU.y, u0.z - aU.z, u0.w - aU.w);
        *(float4*)(sui + c*C + v4) = ui;
        __syncthreads();

        // ---- phase 3: out = aQ + attn @ u_i ----
        float4 aO = aQ;
        #pragma unroll 8
        for (int e = 0; e < C; e++) {
            const float a = sat[c*ASTR + e];
            float4 u4 = *(float4*)(sui + e*C + v4);
            aO.x += a*u4.x; aO.y += a*u4.y; aO.z += a*u4.z; aO.w += a*u4.w;
        }
        *(float4*)(out + bhb + cb + c*D + v0 + v4) = aO;

        // ---- phase 4: S[d, v] += sum_c k[c,d] * u_i[c,v] ----
        // thread owns rows {c, c+32, c+64, c+96} x cols v4..v4+3
        float4 a0 = make_float4(0.f,0.f,0.f,0.f);
        float4 a1 = make_float4(0.f,0.f,0.f,0.f);
        float4 a2 = make_float4(0.f,0.f,0.f,0.f);
        float4 a3 = make_float4(0.f,0.f,0.f,0.f);
        #pragma unroll 4
        for (int e = 0; e < C; e++) {
            float4 u4 = *(float4*)(sui + e*C + v4);
            const float k0 = sk[e*RSTR + c];
            const float k1 = sk[e*RSTR + c + 32];
            const float k2 = sk[e*RSTR + c + 64];
            const float k3 = sk[e*RSTR + c + 96];
            a0.x += k0*u4.x; a0.y += k0*u4.y; a0.z += k0*u4.z; a0.w += k0*u4.w;
            a1.x += k1*u4.x; a1.y += k1*u4.y; a1.z += k1*u4.z; a1.w += k1*u4.w;
            a2.x += k2*u4.x; a2.y += k2*u4.y; a2.z += k2*u4.z; a2.w += k2*u4.w;
            a3.x += k3*u4.x; a3.y += k3*u4.y; a3.z += k3*u4.z; a3.w += k3*u4.w;
        }
        {
            float4* p0 = (float4*)(sS + (c     )*VSLICE + v4);
            float4* p1 = (float4*)(sS + (c + 32)*VSLICE + v4);
            float4* p2 = (float4*)(sS + (c + 64)*VSLICE + v4);
            float4* p3 = (float4*)(sS + (c + 96)*VSLICE + v4);
            float4 t0 = *p0, t1 = *p1, t2 = *p2, t3 = *p3;
            t0.x += a0.x; t0.y += a0.y; t0.z += a0.z; t0.w += a0.w;
            t1.x += a1.x; t1.y += a1.y; t1.z += a1.z; t1.w += a1.w;
            t2.x += a2.x; t2.y += a2.y; t2.z += a2.z; t2.w += a2.w;
            t3.x += a3.x; t3.y += a3.y; t3.z += a3.z; t3.w += a3.w;
            *p0 = t0; *p1 = t1; *p2 = t2; *p3 = t3;
        }
    }
}

// ---------------------------------------------------------------------------
extern "C" void kernel_launch(void* const* d_in, const int* in_sizes, int n_in,
                              void* d_out, int out_size)
{
    const float* q    = (const float*)d_in[0];
    const float* k    = (const float*)d_in[1];
    const float* v    = (const float*)d_in[2];
    const float* beta = (const float*)d_in[3];
    float* out = (float*)d_out;

    const size_t smemA = (size_t)(4 * C * RSTR + C * ASTR) * sizeof(float);
    const size_t smemB = (size_t)(D * VSLICE + 3 * C * RSTR + C * C + C * ASTR + C * C)
                         * sizeof(float);

    cudaFuncSetAttribute(prep_kernel, cudaFuncAttributeMaxDynamicSharedMemorySize,
                         (int)smemA);
    cudaFuncSetAttribute(scan_kernel, cudaFuncAttributeMaxDynamicSharedMemorySize,
                         (int)smemB);

    prep_kernel<<<NC_TOTAL, 256, smemA>>>(q, k, v, beta);
    scan_kernel<<<dim3(NSPLIT, BH), 256, smemB>>>(out);
}

// round 7
// speedup vs baseline: 1.1321x; 1.1276x over previous
#include <cuda_runtime.h>
#include <cstdint>

#define D 128
#define C 32
#define LSEQ 4096
#define BH 32
#define NCHUNK 128              // chunks per (b,h)
#define NC_TOTAL 4096           // total chunks
#define ASTR 36                 // 32x32 matrix row stride (pad 4, 16B-aligned rows)
#define RSTR 132                // 32x128 chunk row stride (pad 4, keeps 16B align)
#define VSLICE 32               // dv slice width per scan CTA
#define NSPLIT 4                // dv splits

// Scratch (allocation-free rule: __device__ globals)
__device__ float g_qn[BH * LSEQ * D];
__device__ float g_kn[BH * LSEQ * D];
__device__ float g_w [BH * LSEQ * D];
__device__ float g_u [BH * LSEQ * D];
__device__ float g_attn[NC_TOTAL * C * C];

// ---------------- packed f32x2 helpers (FFMA2 path, sm_100+) ----------------
__device__ __forceinline__ unsigned long long pk2(float v) {
    unsigned long long r;
    asm("mov.b64 %0, {%1, %1};" : "=l"(r) : "f"(v));
    return r;
}
__device__ __forceinline__ unsigned long long pkf(float lo, float hi) {
    unsigned long long r;
    asm("mov.b64 %0, {%1, %2};" : "=l"(r) : "f"(lo), "f"(hi));
    return r;
}
__device__ __forceinline__ void fma2(unsigned long long& a,
                                     unsigned long long b, unsigned long long c) {
    asm("fma.rn.f32x2 %0, %1, %2, %0;" : "+l"(a) : "l"(b), "l"(c));
}
__device__ __forceinline__ float2 up2(unsigned long long a) {
    float2 f;
    asm("mov.b64 {%0, %1}, %2;" : "=f"(f.x), "=f"(f.y) : "l"(a));
    return f;
}
__device__ __forceinline__ float hadd2(unsigned long long a) {
    float2 f = up2(a); return f.x + f.y;
}
__device__ __forceinline__ void cpa16(uint32_t s, const float* g) {
    asm volatile("cp.async.cg.shared.global [%0], [%1], 16;" :: "r"(s), "l"(g));
}

// ---------------------------------------------------------------------------
// Kernel A: per-chunk preprocessing.
// ---------------------------------------------------------------------------
__global__ void __launch_bounds__(256, 2) prep_kernel(
    const float* __restrict__ q, const float* __restrict__ k,
    const float* __restrict__ v, const float* __restrict__ beta)
{
    extern __shared__ float s[];
    float* sqn = s;                       // 32 x RSTR
    float* skn = sqn + C * RSTR;          // 32 x RSTR
    float* skb = skn + C * RSTR;          // 32 x RSTR
    float* sv  = skb + C * RSTR;          // 32 x RSTR
    float* sA  = sv  + C * RSTR;          // 32 x ASTR

    const int nc  = blockIdx.x;
    const int t   = threadIdx.x;
    const int w   = t >> 5;
    const int lid = t & 31;
    const size_t base = (size_t)nc * (C * D);

    // ---- Phase 1: normalize + scale ----
    #pragma unroll
    for (int rr = 0; rr < 4; rr++) {
        const int r = w * 4 + rr;
        const float bet = __ldg(beta + (size_t)nc * C + r);
        float4 q4 = *(const float4*)(q + base + r * D + lid * 4);
        float4 k4 = *(const float4*)(k + base + r * D + lid * 4);
        float4 v4 = *(const float4*)(v + base + r * D + lid * 4);
        float qs = q4.x*q4.x + q4.y*q4.y + q4.z*q4.z + q4.w*q4.w;
        float ks = k4.x*k4.x + k4.y*k4.y + k4.z*k4.z + k4.w*k4.w;
        #pragma unroll
        for (int o = 16; o > 0; o >>= 1) {
            qs += __shfl_xor_sync(0xffffffffu, qs, o);
            ks += __shfl_xor_sync(0xffffffffu, ks, o);
        }
        const float qr = rsqrtf(qs + 1e-6f);
        const float kr = rsqrtf(ks + 1e-6f);
        float4 qn = make_float4(q4.x*qr, q4.y*qr, q4.z*qr, q4.w*qr);
        float4 kn = make_float4(k4.x*kr, k4.y*kr, k4.z*kr, k4.w*kr);
        float4 kb = make_float4(kn.x*bet, kn.y*bet, kn.z*bet, kn.w*bet);
        float4 vb = make_float4(v4.x*bet, v4.y*bet, v4.z*bet, v4.w*bet);
        *(float4*)(sqn + r * RSTR + lid * 4) = qn;
        *(float4*)(skn + r * RSTR + lid * 4) = kn;
        *(float4*)(skb + r * RSTR + lid * 4) = kb;
        *(float4*)(sv  + r * RSTR + lid * 4) = vb;
        *(float4*)(g_qn + base + r * D + lid * 4) = qn;
        *(float4*)(g_kn + base + r * D + lid * 4) = kn;
    }
    __syncthreads();

    // ---- Phase 2: A (strict-lower, negated) and attn (lower incl diag) ----
    // d-vectorized (float4 broadcasts) + packed f32x2 accumulation.
    {
        const int j  = lid;
        const int i0 = w * 4;
        unsigned long long A0=0,A1=0,A2=0,A3=0,T0=0,T1=0,T2=0,T3=0;
        const float* kjp = skn + j * RSTR;
        const float* b0p = skb + (i0+0) * RSTR;
        const float* b1p = skb + (i0+1) * RSTR;
        const float* b2p = skb + (i0+2) * RSTR;
        const float* b3p = skb + (i0+3) * RSTR;
        const float* q0p = sqn + (i0+0) * RSTR;
        const float* q1p = sqn + (i0+1) * RSTR;
        const float* q2p = sqn + (i0+2) * RSTR;
        const float* q3p = sqn + (i0+3) * RSTR;
        #pragma unroll 4
        for (int d = 0; d < D; d += 4) {
            ulonglong2 kj = *(const ulonglong2*)(kjp + d);
            ulonglong2 b0 = *(const ulonglong2*)(b0p + d);
            ulonglong2 b1 = *(const ulonglong2*)(b1p + d);
            ulonglong2 b2 = *(const ulonglong2*)(b2p + d);
            ulonglong2 b3 = *(const ulonglong2*)(b3p + d);
            fma2(A0, b0.x, kj.x); fma2(A0, b0.y, kj.y);
            fma2(A1, b1.x, kj.x); fma2(A1, b1.y, kj.y);
            fma2(A2, b2.x, kj.x); fma2(A2, b2.y, kj.y);
            fma2(A3, b3.x, kj.x); fma2(A3, b3.y, kj.y);
            ulonglong2 c0 = *(const ulonglong2*)(q0p + d);
            ulonglong2 c1 = *(const ulonglong2*)(q1p + d);
            ulonglong2 c2 = *(const ulonglong2*)(q2p + d);
            ulonglong2 c3 = *(const ulonglong2*)(q3p + d);
            fma2(T0, c0.x, kj.x); fma2(T0, c0.y, kj.y);
            fma2(T1, c1.x, kj.x); fma2(T1, c1.y, kj.y);
            fma2(T2, c2.x, kj.x); fma2(T2, c2.y, kj.y);
            fma2(T3, c3.x, kj.x); fma2(T3, c3.y, kj.y);
        }
        const float a0 = hadd2(A0), a1 = hadd2(A1), a2 = hadd2(A2), a3 = hadd2(A3);
        const float t0 = hadd2(T0), t1 = hadd2(T1), t2 = hadd2(T2), t3 = hadd2(T3);
        float* ga = g_attn + (size_t)nc * (C * C);
        sA[(i0+0)*ASTR + j] = (j < i0+0) ? -a0 : 0.f;
        sA[(i0+1)*ASTR + j] = (j < i0+1) ? -a1 : 0.f;
        sA[(i0+2)*ASTR + j] = (j < i0+2) ? -a2 : 0.f;
        sA[(i0+3)*ASTR + j] = (j < i0+3) ? -a3 : 0.f;
        ga[(i0+0)*C + j] = (j <= i0+0) ? t0 : 0.f;
        ga[(i0+1)*C + j] = (j <= i0+1) ? t1 : 0.f;
        ga[(i0+2)*C + j] = (j <= i0+2) ? t2 : 0.f;
        ga[(i0+3)*C + j] = (j <= i0+3) ? t3 : 0.f;
    }
    __syncthreads();

    // ---- Phase 3: forward substitution (warp 0; lane j owns column j) ----
    if (w == 0) {
        const int j = lid;
        for (int i = 1; i < C; i++) {
            float acc = 0.f;
            for (int kk = j + 1; kk < i; kk++)
                acc += sA[i*ASTR + kk] * sA[kk*ASTR + j];
            __syncwarp();
            if (j < i) sA[i*ASTR + j] += acc;
            __syncwarp();
        }
        sA[j*ASTR + j] = 1.0f;
    }
    __syncthreads();

    // ---- Phase 4: u = inv@v , w = inv@kb (f32x2 + vectorized sA row) ----
    {
        const int i  = t >> 3;
        const int dl = (t & 7) * 4;
        #pragma unroll
        for (int db = 0; db < 4; db++) {
            const int d = db * 32 + dl;
            unsigned long long au01=0, au23=0, aw01=0, aw23=0;
            #pragma unroll 4
            for (int j0 = 0; j0 < C; j0 += 4) {
                float4 a4 = *(const float4*)(sA + i*ASTR + j0);
                #pragma unroll
                for (int jj = 0; jj < 4; jj++) {
                    const float av = (&a4.x)[jj];
                    unsigned long long a2 = pk2(av);
                    ulonglong2 v2 = *(const ulonglong2*)(sv  + (j0+jj)*RSTR + d);
                    ulonglong2 b2 = *(const ulonglong2*)(skb + (j0+jj)*RSTR + d);
                    fma2(au01, a2, v2.x); fma2(au23, a2, v2.y);
                    fma2(aw01, a2, b2.x); fma2(aw23, a2, b2.y);
                }
            }
            float2 l, h;
            l = up2(au01); h = up2(au23);
            *(float4*)(g_u + base + i*D + d) = make_float4(l.x, l.y, h.x, h.y);
            l = up2(aw01); h = up2(aw23);
            *(float4*)(g_w + base + i*D + d) = make_float4(l.x, l.y, h.x, h.y);
        }
    }
}

// ---------------------------------------------------------------------------
// Scan kernel: sequential over chunks, parallel over (b,h) x dv-slices.
// Double-buffered cp.async tile prefetch + 2-row register tiling in phase 2.
// ---------------------------------------------------------------------------
#define SBUF (3 * C * RSTR + 2 * C * ASTR)   // q,k,w tiles + u0 + attn per buffer

__device__ __forceinline__ void prefetch_chunk(
    uint32_t smb, int ci, int w, int lid, int c, int v4, int v0,
    const float* gq, const float* gk, const float* gw,
    const float* gu, const float* ga)
{
    const size_t cb = (size_t)ci * (C * D);
    const uint32_t OK  = (uint32_t)(C * RSTR) * 4u;
    const uint32_t OW  = 2u * OK;
    const uint32_t OU0 = 3u * OK;
    const uint32_t OAT = OU0 + (uint32_t)(C * ASTR) * 4u;
    #pragma unroll
    for (int rr = 0; rr < 4; rr++) {
        const int r = w * 4 + rr;
        const uint32_t off = (uint32_t)(r * RSTR + lid * 4) * 4u;
        cpa16(smb +      off, gq + cb + r * D + lid * 4);
        cpa16(smb + OK + off, gk + cb + r * D + lid * 4);
        cpa16(smb + OW + off, gw + cb + r * D + lid * 4);
    }
    cpa16(smb + OU0 + (uint32_t)(c * ASTR + v4) * 4u, gu + cb + c * D + v0 + v4);
    cpa16(smb + OAT + (uint32_t)(c * ASTR + v4) * 4u, ga + (size_t)ci * (C * C) + c * C + v4);
    asm volatile("cp.async.commit_group;");
}

__global__ void __launch_bounds__(256, 1) scan_kernel(float* __restrict__ out)
{
    extern __shared__ float s[];
    float* sS  = s;                         // 128 x VSLICE
    float* sb0 = sS + D * VSLICE;
    float* sb1 = sb0 + SBUF;
    float* sui = sb1 + SBUF;                // 32 x ASTR
    float* sPU = sui + C * ASTR;            // 32 x ASTR (dh1 partial of w@S)
    float* sPQ = sPU + C * ASTR;            // 32 x ASTR (partial then total q@S)

    const int bh  = blockIdx.y;
    const int v0  = blockIdx.x * VSLICE;
    const int t   = threadIdx.x;
    const int w   = t >> 5;
    const int lid = t & 31;
    // phase-2 mapping: 2 c-rows per thread, d split across halves
    const int dh  = t >> 7;                 // 0/1 -> d in [0,64) / [64,128)
    const int c0  = ((t >> 3) & 15) * 2;
    const int c1  = c0 + 1;
    // phase-3/4 mapping
    const int c   = t >> 3;
    const int v4  = (t & 7) * 4;

    // zero S
    #pragma unroll
    for (int r = 0; r < 4; r++)
        *(float4*)(sS + (r * 256 + t) * 4) = make_float4(0.f, 0.f, 0.f, 0.f);

    const uint32_t smb0 = (uint32_t)__cvta_generic_to_shared(sb0);
    const uint32_t smb1 = (uint32_t)__cvta_generic_to_shared(sb1);

    const size_t bhb = (size_t)bh * LSEQ * D;
    const float* gq = g_qn + bhb;
    const float* gk = g_kn + bhb;
    const float* gw = g_w  + bhb;
    const float* gu = g_u  + bhb;
    const float* ga = g_attn + (size_t)bh * NCHUNK * (C * C);

    prefetch_chunk(smb0, 0, w, lid, c, v4, v0, gq, gk, gw, gu, ga);

    for (int ci = 0; ci < NCHUNK; ci++) {
        float* B = (ci & 1) ? sb1 : sb0;
        const uint32_t smn = (ci & 1) ? smb0 : smb1;
        const float* sq  = B;
        const float* sk  = B + C * RSTR;
        const float* sw  = B + 2 * C * RSTR;
        const float* su0 = B + 3 * C * RSTR;
        const float* sat = su0 + C * ASTR;

        asm volatile("cp.async.wait_group 0;");
        __syncthreads();                        // tiles ready + prev S update done

        const int cn = (ci + 1 < NCHUNK) ? ci + 1 : ci;
        prefetch_chunk(smn, cn, w, lid, c, v4, v0, gq, gk, gw, gu, ga);

        // ---- phase 2: half-d GEMV, 2 rows/thread ----
        unsigned long long aU0x=0,aU0y=0,aU1x=0,aU1y=0;
        unsigned long long aQ0x=0,aQ0y=0,aQ1x=0,aQ1y=0;
        {
            const int dbeg = dh * 64;
            const float* w0p = sw + c0 * RSTR + dbeg;
            const float* w1p = sw + c1 * RSTR + dbeg;
            const float* q0p = sq + c0 * RSTR + dbeg;
            const float* q1p = sq + c1 * RSTR + dbeg;
            const float* Sp  = sS + dbeg * VSLICE + v4;
            #pragma unroll 8
            for (int d = 0; d < 64; d++) {
                ulonglong2 sv2 = *(const ulonglong2*)(Sp + d * VSLICE);
                unsigned long long wv0 = pk2(w0p[d]);
                unsigned long long wv1 = pk2(w1p[d]);
                unsigned long long qv0 = pk2(q0p[d]);
                unsigned long long qv1 = pk2(q1p[d]);
                fma2(aU0x, wv0, sv2.x); fma2(aU0y, wv0, sv2.y);
                fma2(aU1x, wv1, sv2.x); fma2(aU1y, wv1, sv2.y);
                fma2(aQ0x, qv0, sv2.x); fma2(aQ0y, qv0, sv2.y);
                fma2(aQ1x, qv1, sv2.x); fma2(aQ1y, qv1, sv2.y);
            }
        }
        if (dh) {                               // store partials (d in [64,128))
            float2 l, h;
            l = up2(aU0x); h = up2(aU0y);
            *(float4*)(sPU + c0 * ASTR + v4) = make_float4(l.x, l.y, h.x, h.y);
            l = up2(aU1x); h = up2(aU1y);
            *(float4*)(sPU + c1 * ASTR + v4) = make_float4(l.x, l.y, h.x, h.y);
            l = up2(aQ0x); h = up2(aQ0y);
            *(float4*)(sPQ + c0 * ASTR + v4) = make_float4(l.x, l.y, h.x, h.y);
            l = up2(aQ1x); h = up2(aQ1y);
            *(float4*)(sPQ + c1 * ASTR + v4) = make_float4(l.x, l.y, h.x, h.y);
        }
        __syncthreads();
        if (!dh) {                              // combine halves, u_i, total q@S
            float4 pU0 = *(float4*)(sPU + c0 * ASTR + v4);
            float4 pU1 = *(float4*)(sPU + c1 * ASTR + v4);
            float4 pQ0 = *(float4*)(sPQ + c0 * ASTR + v4);
            float4 pQ1 = *(float4*)(sPQ + c1 * ASTR + v4);
            float4 u00 = *(const float4*)(su0 + c0 * ASTR + v4);
            float4 u01 = *(const float4*)(su0 + c1 * ASTR + v4);
            float2 l, h;
            l = up2(aU0x); h = up2(aU0y);
            *(float4*)(sui + c0 * ASTR + v4) = make_float4(
                u00.x - (l.x + pU0.x), u00.y - (l.y + pU0.y),
                u00.z - (h.x + pU0.z), u00.w - (h.y + pU0.w));
            l = up2(aU1x); h = up2(aU1y);
            *(float4*)(sui + c1 * ASTR + v4) = make_float4(
                u01.x - (l.x + pU1.x), u01.y - (l.y + pU1.y),
                u01.z - (h.x + pU1.z), u01.w - (h.y + pU1.w));
            l = up2(aQ0x); h = up2(aQ0y);
            *(float4*)(sPQ + c0 * ASTR + v4) = make_float4(
                l.x + pQ0.x, l.y + pQ0.y, h.x + pQ0.z, h.y + pQ0.w);
            l = up2(aQ1x); h = up2(aQ1y);
            *(float4*)(sPQ + c1 * ASTR + v4) = make_float4(
                l.x + pQ1.x, l.y + pQ1.y, h.x + pQ1.z, h.y + pQ1.w);
        }
        __syncthreads();

        // ---- phase 3: out = q@S + attn @ u_i ----
        {
            float4 a0 = *(const float4*)(sPQ + c * ASTR + v4);
            unsigned long long o01 = pkf(a0.x, a0.y);
            unsigned long long o23 = pkf(a0.z, a0.w);
            #pragma unroll 8
            for (int e = 0; e < C; e++) {
                unsigned long long a2 = pk2(sat[c * ASTR + e]);
                ulonglong2 u2 = *(const ulonglong2*)(sui + e * ASTR + v4);
                fma2(o01, a2, u2.x); fma2(o23, a2, u2.y);
            }
            float2 l = up2(o01), h = up2(o23);
            *(float4*)(out + bhb + (size_t)ci * (C * D) + c * D + v0 + v4) =
                make_float4(l.x, l.y, h.x, h.y);
        }

        // ---- phase 4: S[d, v] += sum_e k[e,d] * u_i[e,v] ----
        {
            unsigned long long A0=0,A1=0,A2=0,A3=0,A4=0,A5=0,A6=0,A7=0;
            #pragma unroll 4
            for (int e = 0; e < C; e++) {
                ulonglong2 u2 = *(const ulonglong2*)(sui + e * ASTR + v4);
                unsigned long long k0 = pk2(sk[e * RSTR + c]);
                unsigned long long k1 = pk2(sk[e * RSTR + c + 32]);
                unsigned long long k2 = pk2(sk[e * RSTR + c + 64]);
                unsigned long long k3 = pk2(sk[e * RSTR + c + 96]);
                fma2(A0, k0, u2.x); fma2(A1, k0, u2.y);
                fma2(A2, k1, u2.x); fma2(A3, k1, u2.y);
                fma2(A4, k2, u2.x); fma2(A5, k2, u2.y);
                fma2(A6, k3, u2.x); fma2(A7, k3, u2.y);
            }
            float2 l, h;
            float4* p0 = (float4*)(sS + (c      ) * VSLICE + v4);
            float4* p1 = (float4*)(sS + (c +  32) * VSLICE + v4);
            float4* p2 = (float4*)(sS + (c +  64) * VSLICE + v4);
            float4* p3 = (float4*)(sS + (c +  96) * VSLICE + v4);
            float4 t0 = *p0, t1 = *p1, t2 = *p2, t3 = *p3;
            l = up2(A0); h = up2(A1);
            t0.x += l.x; t0.y += l.y; t0.z += h.x; t0.w += h.y;
            l = up2(A2); h = up2(A3);
            t1.x += l.x; t1.y += l.y; t1.z += h.x; t1.w += h.y;
            l = up2(A4); h = up2(A5);
            t2.x += l.x; t2.y += l.y; t2.z += h.x; t2.w += h.y;
            l = up2(A6); h = up2(A7);
            t3.x += l.x; t3.y += l.y; t3.z += h.x; t3.w += h.y;
            *p0 = t0; *p1 = t1; *p2 = t2; *p3 = t3;
        }
    }
}

// ---------------------------------------------------------------------------
extern "C" void kernel_launch(void* const* d_in, const int* in_sizes, int n_in,
                              void* d_out, int out_size)
{
    const float* q    = (const float*)d_in[0];
    const float* k    = (const float*)d_in[1];
    const float* v    = (const float*)d_in[2];
    const float* beta = (const float*)d_in[3];
    float* out = (float*)d_out;

    const size_t smemA = (size_t)(4 * C * RSTR + C * ASTR) * sizeof(float);
    const size_t smemB = (size_t)(D * VSLICE + 2 * SBUF + 3 * C * ASTR)
                         * sizeof(float);

    cudaFuncSetAttribute(prep_kernel, cudaFuncAttributeMaxDynamicSharedMemorySize,
                         (int)smemA);
    cudaFuncSetAttribute(scan_kernel, cudaFuncAttributeMaxDynamicSharedMemorySize,
                         (int)smemB);

    prep_kernel<<<NC_TOTAL, 256, smemA>>>(q, k, v, beta);
    scan_kernel<<<dim3(NSPLIT, BH), 256, smemB>>>(out);
}